// round 13
// baseline (speedup 1.0000x reference)
#include <cuda_runtime.h>
#include <cuda_fp16.h>
#include <cuda_fp8.h>
#include <mma.h>
#include <stdint.h>

using namespace nvcuda;

#define NN 50000
#define EE 800000
#define HH 128
#define CC 10
#define LL 3
#define OO 2
#define KHOP 10
#define GG 128
#define NH ((size_t)NN * HH)
#define NB ((size_t)NN * 128)            // bytes per fp8 z slot
#define ZH16B ((size_t)4 * NH)           // bytes per order of fp16 z (2 slots)
#define Z8B9 ((size_t)9 * NB)            // bytes per order of fp8 z (9 slots)

// ---------------- fp8 helpers ----------------
__device__ __forceinline__ float2 fp8x2_to_float2(uint32_t v) {
    __half2_raw hr = __nv_cvt_fp8x2_to_halfraw2((__nv_fp8x2_storage_t)v, __NV_E4M3);
    __half2 h = *(__half2*)&hr;
    return __half22float2(h);
}
__device__ __forceinline__ uint32_t float2_to_fp8x2(float x, float y) {
    return (uint32_t)__nv_cvt_float2_to_fp8x2(make_float2(x, y), __NV_SATFINITE, __NV_E4M3);
}

// ---------------- scratch ----------------
__device__ __half  g_x16[NH];
__device__ __half  g_zh16[OO * 2 * NH];      // fp16 slots 0,1 per order
__device__ uint8_t g_z8[OO * Z8B9];          // fp8 slots (logical k=2..10) per order
__device__ __half  g_t16[NH];
__device__ __half  g_h16[NH];
__device__ __half  g_win16[LL * OO * HH * HH];
__device__ __half  g_wfold16[LL * 256 * HH];
__device__ float   g_bfold[LL * HH];
__device__ __half  g_wn216[LL * HH * HH];
__device__ int     g_rowptr[OO * (NN + 1)];
__device__ int     g_cursor[OO * NN];
__device__ int2    g_epair[OO * EE];         // (src, weight-bits) interleaved
__device__ float   g_pool[GG * HH];
__device__ float   g_p1[GG * HH];

// ---------------- CSR build (batched over orders) ----------------
__global__ void csr_count(const int* __restrict__ eidx, int* __restrict__ cntB) {
    int o = blockIdx.y;
    const int* dst = eidx + (size_t)o * 2 * EE;
    int* cnt = cntB + (size_t)o * NN;
    int e = blockIdx.x * blockDim.x + threadIdx.x;
    if (e < EE) atomicAdd(&cnt[dst[e]], 1);
}

__global__ void csr_scan(int* __restrict__ cntB, int* __restrict__ rowptrB) {
    int o = blockIdx.y;
    int* cnt = cntB + (size_t)o * NN;
    int* rowptr = rowptrB + (size_t)o * (NN + 1);
    __shared__ int sdata[1024];
    __shared__ int sbase;
    int t = threadIdx.x;
    if (t == 0) { rowptr[0] = 0; sbase = 0; }
    __syncthreads();
    for (int c = 0; c < NN; c += 1024) {
        int v = (c + t < NN) ? cnt[c + t] : 0;
        sdata[t] = v;
        __syncthreads();
        for (int off = 1; off < 1024; off <<= 1) {
            int add = (t >= off) ? sdata[t - off] : 0;
            __syncthreads();
            sdata[t] += add;
            __syncthreads();
        }
        if (c + t < NN) {
            rowptr[c + t + 1] = sbase + sdata[t];
            cnt[c + t] = sbase + sdata[t] - v;   // exclusive prefix -> cursor
        }
        __syncthreads();
        if (t == 0) sbase += sdata[1023];
        __syncthreads();
    }
}

__global__ void csr_fill(const int* __restrict__ eidx, const float* __restrict__ ewB,
                         int* __restrict__ cursorB, int2* __restrict__ epairB) {
    int o = blockIdx.y;
    const int* dst = eidx + (size_t)o * 2 * EE;
    const int* src = dst + EE;
    const float* w = ewB + (size_t)o * EE;
    int* cursor = cursorB + (size_t)o * NN;
    int2* ep = epairB + (size_t)o * EE;
    int e = blockIdx.x * blockDim.x + threadIdx.x;
    if (e < EE) {
        int pos = atomicAdd(&cursor[dst[e]], 1);
        ep[pos] = make_int2(src[e], __float_as_int(w[e]));
    }
}

// ---------------- casts + weight prep ----------------
__global__ void cast_f2h(const float* __restrict__ src, __half* __restrict__ dst, int n) {
    int i = blockIdx.x * blockDim.x + threadIdx.x;
    int i4 = i * 4;
    if (i4 + 3 < n) {
        float4 v = *(const float4*)(src + i4);
        __half2 h0 = __floats2half2_rn(v.x, v.y);
        __half2 h1 = __floats2half2_rn(v.z, v.w);
        *(uint2*)(dst + i4) = make_uint2(*(uint32_t*)&h0, *(uint32_t*)&h1);
    } else {
        for (int j = i4; j < n; j++) dst[j] = __float2half(src[j]);
    }
}

__global__ void fold_w(const float* __restrict__ Wout, const float* __restrict__ Wn1,
                       __half* __restrict__ Wfold) {
    int l = blockIdx.y;
    int idx = blockIdx.x * blockDim.x + threadIdx.x;
    if (idx >= 256 * 128) return;
    int k = idx >> 7, j = idx & 127;
    const float* wo = Wout + (size_t)l * 256 * 128 + (size_t)k * 128;
    const float* wn = Wn1 + (size_t)l * 128 * 128 + j;
    float a0 = 0.f, a1 = 0.f, a2 = 0.f, a3 = 0.f;
#pragma unroll 8
    for (int m = 0; m < 128; m += 4) {
        a0 = fmaf(wo[m],     wn[(size_t)m * 128],       a0);
        a1 = fmaf(wo[m + 1], wn[(size_t)(m + 1) * 128], a1);
        a2 = fmaf(wo[m + 2], wn[(size_t)(m + 2) * 128], a2);
        a3 = fmaf(wo[m + 3], wn[(size_t)(m + 3) * 128], a3);
    }
    Wfold[(size_t)l * 256 * 128 + idx] = __float2half((a0 + a1) + (a2 + a3));
}

__global__ void fold_b(const float* __restrict__ b_out, const float* __restrict__ Wn1,
                       const float* __restrict__ bn1, float* __restrict__ bf) {
    int l = blockIdx.y;
    int j = threadIdx.x;
    const float* bo = b_out + (size_t)l * 128;
    const float* wn = Wn1 + (size_t)l * 128 * 128 + j;
    float acc = bn1[(size_t)l * 128 + j];
    for (int m = 0; m < 128; m++) acc = fmaf(bo[m], wn[(size_t)m * 128], acc);
    bf[(size_t)l * 128 + j] = acc;
}

// ---------------- shared GEMM mainloop helpers ----------------
#define GEMM_PROLOG() \
    extern __shared__ char smem[]; \
    __half* As = (__half*)smem; \
    __half* Bs = (__half*)(smem + 128 * 136 * 2); \
    float*  Cs = (float*)smem; \
    const int tid = threadIdx.x; \
    const int warp = tid >> 5; \
    const int warpM = warp >> 1; \
    const int warpN = warp & 1; \
    const int rowBase = blockIdx.x * 128; \
    wmma::fragment<wmma::accumulator, 16, 16, 16, float> acc[2][4]; \
    _Pragma("unroll") for (int i = 0; i < 2; i++) \
    _Pragma("unroll") for (int j = 0; j < 4; j++) wmma::fill_fragment(acc[i][j], 0.f);

#define GEMM_MMA_CHUNK() do { \
    __syncthreads(); \
    _Pragma("unroll") \
    for (int ks = 0; ks < 8; ks++) { \
        int k0 = ks * 16; \
        wmma::fragment<wmma::matrix_a, 16, 16, 16, __half, wmma::row_major> af[2]; \
        wmma::fragment<wmma::matrix_b, 16, 16, 16, __half, wmma::row_major> bf[4]; \
        _Pragma("unroll") for (int i = 0; i < 2; i++) \
            wmma::load_matrix_sync(af[i], As + (warpM * 32 + i * 16) * 136 + k0, 136); \
        _Pragma("unroll") for (int j = 0; j < 4; j++) \
            wmma::load_matrix_sync(bf[j], Bs + k0 * 136 + warpN * 64 + j * 16, 136); \
        _Pragma("unroll") for (int i = 0; i < 2; i++) \
        _Pragma("unroll") for (int j = 0; j < 4; j++) \
            wmma::mma_sync(acc[i][j], af[i], bf[j], acc[i][j]); \
    } \
    __syncthreads(); \
} while (0)

#define GEMM_STORE_ACC() do { \
    _Pragma("unroll") for (int i = 0; i < 2; i++) \
    _Pragma("unroll") for (int j = 0; j < 4; j++) \
        wmma::store_matrix_sync(Cs + (warpM * 32 + i * 16) * 132 + warpN * 64 + j * 16, \
                                acc[i][j], 132, wmma::mem_row_major); \
    __syncthreads(); \
} while (0)

__device__ __forceinline__ void gemm_epilogue(
    float* Cs, int tid, int rowBase,
    const float* bias, const float* gam, const float* bet,
    __half* out)
{
    const float RS = 0.9999950000374997f;  // 1/sqrt(1+1e-5)
    const int r = tid >> 1;
    const int cb0 = (tid & 1) * 64;
    const int grow = rowBase + r;
    if (grow >= NN) return;
#pragma unroll
    for (int j = 0; j < 8; j++) {
        int c0 = cb0 + j * 8;
        float4 v0 = *(const float4*)(Cs + r * 132 + c0);
        float4 v1 = *(const float4*)(Cs + r * 132 + c0 + 4);
        float t[8] = {v0.x, v0.y, v0.z, v0.w, v1.x, v1.y, v1.z, v1.w};
#pragma unroll
        for (int q = 0; q < 8; q++) {
            int c = c0 + q;
            t[q] += bias[c];
            if (gam) t[q] = fmaxf(t[q] * gam[c] * RS + bet[c], 0.f);
        }
        __half2 h0 = __floats2half2_rn(t[0], t[1]);
        __half2 h1 = __floats2half2_rn(t[2], t[3]);
        __half2 h2 = __floats2half2_rn(t[4], t[5]);
        __half2 h3 = __floats2half2_rn(t[6], t[7]);
        *(uint4*)(out + (size_t)grow * 128 + c0) =
            make_uint4(*(uint32_t*)&h0, *(uint32_t*)&h1, *(uint32_t*)&h2, *(uint32_t*)&h3);
    }
}

// ---------------- standard wmma GEMM, K=128 (multi-order via blockIdx.y) ----------------
__global__ __launch_bounds__(256) void gemm16(
    const __half* __restrict__ A,
    const __half* __restrict__ Bb, size_t Bstride,
    const float* __restrict__ biasb, size_t biasStride,
    __half* __restrict__ outb, size_t outStride,
    const float* __restrict__ gam, const float* __restrict__ bet)
{
    GEMM_PROLOG();
    const int o = blockIdx.y;
    const __half* B = Bb + (size_t)o * Bstride;
#pragma unroll
    for (int it = 0; it < 8; it++) {
        int idx = it * 256 + tid;
        int r = idx >> 4;
        int c8 = (idx & 15) * 8;
        int grow = rowBase + r;
        uint4 av = make_uint4(0, 0, 0, 0);
        if (grow < NN) av = *(const uint4*)(A + (size_t)grow * 128 + c8);
        *(uint4*)(As + r * 136 + c8) = av;
        *(uint4*)(Bs + r * 136 + c8) = *(const uint4*)(B + (size_t)r * 128 + c8);
    }
    GEMM_MMA_CHUNK();
    GEMM_STORE_ACC();
    gemm_epilogue(Cs, tid, rowBase, biasb + (size_t)o * biasStride, gam, bet,
                  outb + (size_t)o * outStride);
}

// ---- fused combine+GEMM: t = relu(bn1( (fW0·z0 + fW1·z1 + Σ_j fW[j+2]·2^-(j+1)·z8_j) @ Wfold + bfold ))
__global__ __launch_bounds__(256) void gemm_fold(
    const __half* __restrict__ zh16,        // 2 fp16 slots per order
    const uint8_t* __restrict__ z8,         // 9 fp8 slots per order
    const float* __restrict__ fWl,
    const __half* __restrict__ B,
    const float* __restrict__ bias,
    __half* __restrict__ out,
    const float* __restrict__ gam, const float* __restrict__ bet)
{
    GEMM_PROLOG();
    for (int kc = 0; kc < 2; kc++) {        // chunk kc == order kc
        const __half* z16 = zh16 + (size_t)kc * 2 * NH;
        const uint8_t* z8o = z8 + (size_t)kc * Z8B9;
        float fw16[2];
        fw16[0] = __ldg(fWl + kc * (KHOP + 1) + 0);
        fw16[1] = __ldg(fWl + kc * (KHOP + 1) + 1);
        float fw8[9];
        float sc = 0.5f;
#pragma unroll
        for (int j = 0; j < 9; j++) { fw8[j] = __ldg(fWl + kc * (KHOP + 1) + j + 2) * sc; sc *= 0.5f; }
#pragma unroll
        for (int it = 0; it < 8; it++) {
            int idx = it * 256 + tid;
            int r = idx >> 4;
            int c8 = (idx & 15) * 8;
            int grow = rowBase + r;
            float fa[8] = {0, 0, 0, 0, 0, 0, 0, 0};
            if (grow < NN) {
                size_t off = (size_t)grow * 128 + c8;
#pragma unroll
                for (int s = 0; s < 2; s++) {
                    uint4 u = *(const uint4*)(z16 + (size_t)s * NH + off);
                    float f = fw16[s];
                    float2 p0 = __half22float2(*(__half2*)&u.x);
                    float2 p1 = __half22float2(*(__half2*)&u.y);
                    float2 p2 = __half22float2(*(__half2*)&u.z);
                    float2 p3 = __half22float2(*(__half2*)&u.w);
                    fa[0] = fmaf(f, p0.x, fa[0]); fa[1] = fmaf(f, p0.y, fa[1]);
                    fa[2] = fmaf(f, p1.x, fa[2]); fa[3] = fmaf(f, p1.y, fa[3]);
                    fa[4] = fmaf(f, p2.x, fa[4]); fa[5] = fmaf(f, p2.y, fa[5]);
                    fa[6] = fmaf(f, p3.x, fa[6]); fa[7] = fmaf(f, p3.y, fa[7]);
                }
#pragma unroll
                for (int j = 0; j < 9; j++) {
                    uint2 u = *(const uint2*)(z8o + (size_t)j * NB + off);
                    float f = fw8[j];
                    float2 p0 = fp8x2_to_float2(u.x & 0xFFFF);
                    float2 p1 = fp8x2_to_float2(u.x >> 16);
                    float2 p2 = fp8x2_to_float2(u.y & 0xFFFF);
                    float2 p3 = fp8x2_to_float2(u.y >> 16);
                    fa[0] = fmaf(f, p0.x, fa[0]); fa[1] = fmaf(f, p0.y, fa[1]);
                    fa[2] = fmaf(f, p1.x, fa[2]); fa[3] = fmaf(f, p1.y, fa[3]);
                    fa[4] = fmaf(f, p2.x, fa[4]); fa[5] = fmaf(f, p2.y, fa[5]);
                    fa[6] = fmaf(f, p3.x, fa[6]); fa[7] = fmaf(f, p3.y, fa[7]);
                }
            }
            __half2 h0 = __floats2half2_rn(fa[0], fa[1]);
            __half2 h1 = __floats2half2_rn(fa[2], fa[3]);
            __half2 h2 = __floats2half2_rn(fa[4], fa[5]);
            __half2 h3 = __floats2half2_rn(fa[6], fa[7]);
            *(uint4*)(As + r * 136 + c8) =
                make_uint4(*(uint32_t*)&h0, *(uint32_t*)&h1, *(uint32_t*)&h2, *(uint32_t*)&h3);
            *(uint4*)(Bs + r * 136 + c8) = *(const uint4*)(B + (size_t)(kc * 128 + r) * 128 + c8);
        }
        GEMM_MMA_CHUNK();
    }
    GEMM_STORE_ACC();
    gemm_epilogue(Cs, tid, rowBase, bias, gam, bet, out);
}

// ---------------- SpMM hop template (IN8/OUT8 select z dtype; OUT8 applies 2x renorm) ----------
template <bool IN8, bool OUT8>
__global__ __launch_bounds__(256) void spmm_hop_t(
    const int* __restrict__ rowptrB,
    const int2* __restrict__ epairB,
    const uint8_t* __restrict__ zinB, size_t zinOS,
    uint8_t* __restrict__ zoutB, size_t zoutOS)
{
    const int o = blockIdx.y;
    const int* rowptr = rowptrB + (size_t)o * (NN + 1);
    const int2* ep = epairB + (size_t)o * EE;
    const uint8_t* zin = zinB + (size_t)o * zinOS;
    uint8_t* zout = zoutB + (size_t)o * zoutOS;

    int warp = (blockIdx.x * blockDim.x + threadIdx.x) >> 5;
    int lane = threadIdx.x & 31;
    if (warp >= NN) return;
    int beg = rowptr[warp], end = rowptr[warp + 1];

    float ax = 0.f, ay = 0.f, az = 0.f, aw = 0.f;
    int e = beg;
    for (; e + 4 <= end; e += 4) {
        int2 p0 = ep[e], p1 = ep[e + 1], p2 = ep[e + 2], p3 = ep[e + 3];
        float w0 = __int_as_float(p0.y), w1 = __int_as_float(p1.y);
        float w2 = __int_as_float(p2.y), w3 = __int_as_float(p3.y);
        float2 a0, b0, a1, b1, a2, b2, a3, b3;
        if (IN8) {
            uint32_t u0 = *(const uint32_t*)(zin + (size_t)p0.x * 128 + lane * 4);
            uint32_t u1 = *(const uint32_t*)(zin + (size_t)p1.x * 128 + lane * 4);
            uint32_t u2 = *(const uint32_t*)(zin + (size_t)p2.x * 128 + lane * 4);
            uint32_t u3 = *(const uint32_t*)(zin + (size_t)p3.x * 128 + lane * 4);
            a0 = fp8x2_to_float2(u0 & 0xFFFF); b0 = fp8x2_to_float2(u0 >> 16);
            a1 = fp8x2_to_float2(u1 & 0xFFFF); b1 = fp8x2_to_float2(u1 >> 16);
            a2 = fp8x2_to_float2(u2 & 0xFFFF); b2 = fp8x2_to_float2(u2 >> 16);
            a3 = fp8x2_to_float2(u3 & 0xFFFF); b3 = fp8x2_to_float2(u3 >> 16);
        } else {
            uint2 u0 = *(const uint2*)(zin + (size_t)p0.x * 256 + lane * 8);
            uint2 u1 = *(const uint2*)(zin + (size_t)p1.x * 256 + lane * 8);
            uint2 u2 = *(const uint2*)(zin + (size_t)p2.x * 256 + lane * 8);
            uint2 u3 = *(const uint2*)(zin + (size_t)p3.x * 256 + lane * 8);
            a0 = __half22float2(*(__half2*)&u0.x); b0 = __half22float2(*(__half2*)&u0.y);
            a1 = __half22float2(*(__half2*)&u1.x); b1 = __half22float2(*(__half2*)&u1.y);
            a2 = __half22float2(*(__half2*)&u2.x); b2 = __half22float2(*(__half2*)&u2.y);
            a3 = __half22float2(*(__half2*)&u3.x); b3 = __half22float2(*(__half2*)&u3.y);
        }
        ax = fmaf(w0, a0.x, fmaf(w1, a1.x, fmaf(w2, a2.x, fmaf(w3, a3.x, ax))));
        ay = fmaf(w0, a0.y, fmaf(w1, a1.y, fmaf(w2, a2.y, fmaf(w3, a3.y, ay))));
        az = fmaf(w0, b0.x, fmaf(w1, b1.x, fmaf(w2, b2.x, fmaf(w3, b3.x, az))));
        aw = fmaf(w0, b0.y, fmaf(w1, b1.y, fmaf(w2, b2.y, fmaf(w3, b3.y, aw))));
    }
    for (; e < end; ++e) {
        int2 p = ep[e];
        float w = __int_as_float(p.y);
        float2 a, b;
        if (IN8) {
            uint32_t u = *(const uint32_t*)(zin + (size_t)p.x * 128 + lane * 4);
            a = fp8x2_to_float2(u & 0xFFFF); b = fp8x2_to_float2(u >> 16);
        } else {
            uint2 u = *(const uint2*)(zin + (size_t)p.x * 256 + lane * 8);
            a = __half22float2(*(__half2*)&u.x); b = __half22float2(*(__half2*)&u.y);
        }
        ax = fmaf(w, a.x, ax); ay = fmaf(w, a.y, ay);
        az = fmaf(w, b.x, az); aw = fmaf(w, b.y, aw);
    }

    if (OUT8) {
        // 2x renorm per fp8 store; compensated by 2^-(k-1) weights in combine
        uint32_t pk = float2_to_fp8x2(2.f * ax, 2.f * ay) |
                      (float2_to_fp8x2(2.f * az, 2.f * aw) << 16);
        *(uint32_t*)(zout + (size_t)warp * 128 + lane * 4) = pk;
    } else {
        __half2 h0 = __floats2half2_rn(ax, ay);
        __half2 h1 = __floats2half2_rn(az, aw);
        *(uint2*)(zout + (size_t)warp * 256 + lane * 8) = make_uint2(*(uint32_t*)&h0, *(uint32_t*)&h1);
    }
}

// ---------------- pooling + head ----------------
__global__ void pool_kernel(const __half* __restrict__ h, const int* __restrict__ batch,
                            float* __restrict__ p) {
    int idx = blockIdx.x * blockDim.x + threadIdx.x;
    if (idx >= NN * HH) return;
    int node = idx >> 7;
    int f = idx & 127;
    atomicAdd(&p[batch[node] * HH + f], __half2float(h[idx]));
}

__global__ void head1(const float* __restrict__ p, const float* __restrict__ W1,
                      const float* __restrict__ b1, float* __restrict__ p1) {
    int i = blockIdx.x * blockDim.x + threadIdx.x;
    if (i >= GG * HH) return;
    int g = i >> 7, j = i & 127;
    float acc = b1[j];
    for (int k = 0; k < HH; k++)
        acc = fmaf(p[g * HH + k], W1[k * HH + j], acc);
    p1[i] = fmaxf(acc, 0.f);
}

__global__ void head2(const float* __restrict__ p1, const float* __restrict__ W2,
                      const float* __restrict__ b2, float* __restrict__ outp) {
    int i = blockIdx.x * blockDim.x + threadIdx.x;
    if (i >= GG * CC) return;
    int g = i / CC, j = i % CC;
    float acc = b2[j];
    for (int k = 0; k < HH; k++)
        acc = fmaf(p1[g * HH + k], W2[k * CC + j], acc);
    outp[i] = acc;
}

// ---------------- host orchestration ----------------
extern "C" void kernel_launch(void* const* d_in, const int* in_sizes, int n_in,
                              void* d_out, int out_size) {
    const float* x      = (const float*)d_in[0];
    const int*   eidx   = (const int*)  d_in[1];
    const float* ew     = (const float*)d_in[2];
    const int*   batch  = (const int*)  d_in[3];
    const float* W_in   = (const float*)d_in[4];
    const float* b_in   = (const float*)d_in[5];
    const float* fW     = (const float*)d_in[6];
    const float* W_out  = (const float*)d_in[7];
    const float* b_out  = (const float*)d_in[8];
    const float* Wn1    = (const float*)d_in[9];
    const float* bn1    = (const float*)d_in[10];
    const float* g1     = (const float*)d_in[11];
    const float* be1    = (const float*)d_in[12];
    const float* Wn2    = (const float*)d_in[13];
    const float* bn2    = (const float*)d_in[14];
    const float* g2     = (const float*)d_in[15];
    const float* be2    = (const float*)d_in[16];
    const float* W1     = (const float*)d_in[17];
    const float* b1     = (const float*)d_in[18];
    const float* W2     = (const float*)d_in[19];
    const float* b2     = (const float*)d_in[20];
    float* outp = (float*)d_out;

    __half *x16, *zh16, *t16, *h16, *win16, *wfold16, *wn216;
    uint8_t *z8;
    float *bfold, *pool, *p1;
    int *rowptr, *cursor;
    int2 *epair;
    cudaGetSymbolAddress((void**)&x16, g_x16);
    cudaGetSymbolAddress((void**)&zh16, g_zh16);
    cudaGetSymbolAddress((void**)&z8, g_z8);
    cudaGetSymbolAddress((void**)&t16, g_t16);
    cudaGetSymbolAddress((void**)&h16, g_h16);
    cudaGetSymbolAddress((void**)&win16, g_win16);
    cudaGetSymbolAddress((void**)&wfold16, g_wfold16);
    cudaGetSymbolAddress((void**)&bfold, g_bfold);
    cudaGetSymbolAddress((void**)&wn216, g_wn216);
    cudaGetSymbolAddress((void**)&pool, g_pool);
    cudaGetSymbolAddress((void**)&p1, g_p1);
    cudaGetSymbolAddress((void**)&rowptr, g_rowptr);
    cudaGetSymbolAddress((void**)&cursor, g_cursor);
    cudaGetSymbolAddress((void**)&epair, g_epair);

    const size_t WIN_SZ = (size_t)LL * OO * HH * HH;
    const size_t WN_SZ  = (size_t)LL * HH * HH;
    const int EB  = (EE + 255) / 256;
    const int MB  = (NN + 127) / 128;
    const int SB  = ((NN * 32) + 255) / 256;
    const int GEMM_SMEM = 128 * 136 * 2 * 2;

    cudaFuncSetAttribute(gemm16, cudaFuncAttributeMaxDynamicSharedMemorySize, GEMM_SMEM);
    cudaFuncSetAttribute(gemm_fold, cudaFuncAttributeMaxDynamicSharedMemorySize, GEMM_SMEM);

    // ---- weight prep ----
    cast_f2h<<<(int)((WIN_SZ / 4 + 255) / 256), 256>>>(W_in, win16, (int)WIN_SZ);
    cast_f2h<<<(int)((WN_SZ / 4 + 255) / 256), 256>>>(Wn2, wn216, (int)WN_SZ);
    cast_f2h<<<(int)((NH / 4 + 255) / 256), 256>>>(x, x16, (int)NH);
    fold_w<<<dim3((256 * 128 + 255) / 256, LL), 256>>>(W_out, Wn1, wfold16);
    fold_b<<<dim3(1, LL), 128>>>(b_out, Wn1, bn1, bfold);

    // ---- build CSR (both orders batched; scan emits cursor) ----
    cudaMemsetAsync(cursor, 0, (size_t)OO * NN * sizeof(int), 0);
    csr_count<<<dim3(EB, OO), 256>>>(eidx, cursor);
    csr_scan<<<dim3(1, OO), 1024>>>(cursor, rowptr);
    csr_fill<<<dim3(EB, OO), 256>>>(eidx, ew, cursor, epair);

    const uint8_t* zh16b = (const uint8_t*)zh16;

    const __half* hin = x16;
    for (int l = 0; l < LL; l++) {
        // z0 for both orders -> zh16 slot 0 (fp16)
        gemm16<<<dim3(MB, OO), 256, GEMM_SMEM>>>(hin,
                                      win16 + (size_t)l * OO * HH * HH, (size_t)HH * HH,
                                      b_in + (size_t)l * OO * HH, HH,
                                      zh16, (size_t)2 * NH,
                                      nullptr, nullptr);
        for (int k = 0; k < KHOP; k++) {
            dim3 g(SB, OO);
            if (k == 0)
                spmm_hop_t<false, false><<<g, 256>>>(rowptr, epair,
                    zh16b, ZH16B, (uint8_t*)zh16b + NH * 2, ZH16B);
            else if (k == 1)
                spmm_hop_t<false, true><<<g, 256>>>(rowptr, epair,
                    zh16b + NH * 2, ZH16B, z8, Z8B9);
            else
                spmm_hop_t<true, true><<<g, 256>>>(rowptr, epair,
                    z8 + (size_t)(k - 2) * NB, Z8B9, z8 + (size_t)(k - 1) * NB, Z8B9);
        }
        // t = relu(bn1( combine(z) @ Wfold + bfold ))
        gemm_fold<<<dim3(MB, 1), 256, GEMM_SMEM>>>(zh16, z8,
                                      fW + (size_t)l * OO * (KHOP + 1),
                                      wfold16 + (size_t)l * 256 * HH,
                                      bfold + (size_t)l * HH,
                                      t16,
                                      g1 + (size_t)l * HH, be1 + (size_t)l * HH);
        // h = relu(bn2(t @ Wn2 + bn2))
        gemm16<<<dim3(MB, 1), 256, GEMM_SMEM>>>(t16,
                                      wn216 + (size_t)l * HH * HH, 0,
                                      bn2 + (size_t)l * HH, 0,
                                      h16, 0,
                                      g2 + (size_t)l * HH, be2 + (size_t)l * HH);
        hin = h16;
    }

    cudaMemsetAsync(pool, 0, GG * HH * sizeof(float), 0);
    pool_kernel<<<(NN * HH + 255) / 256, 256>>>(h16, batch, pool);
    head1<<<(GG * HH + 255) / 256, 256>>>(pool, W1, b1, p1);
    head2<<<(GG * CC + 255) / 256, 256>>>(p1, W2, b2, outp);
}

// round 14
// speedup vs baseline: 1.0419x; 1.0419x over previous
#include <cuda_runtime.h>
#include <cuda_fp16.h>
#include <mma.h>
#include <stdint.h>

using namespace nvcuda;

#define NN 50000
#define EE 800000
#define HH 128
#define CC 10
#define LL 3
#define OO 2
#define KHOP 10
#define GG 128
#define NH ((size_t)NN * HH)
#define ZSTRIDE ((size_t)(KHOP + 1) * NH)

// ---------------- scratch ----------------
__device__ __half g_x16[NH];
__device__ __half g_zh[OO * ZSTRIDE];
__device__ __half g_t16[NH];
__device__ __half g_h16[NH];
__device__ __half g_win16[LL * OO * HH * HH];
__device__ __half g_wfold16[LL * 256 * HH];
__device__ float  g_bfold[LL * HH];
__device__ __half g_wn216[LL * HH * HH];
__device__ int    g_rowptr[OO * (NN + 1)];
__device__ int    g_cursor[OO * NN];
__device__ int2   g_epair[OO * EE];          // (src, weight-bits) interleaved
__device__ float  g_pool[GG * HH];
__device__ float  g_p1[GG * HH];

// ---------------- CSR build (batched over orders) ----------------
__global__ void csr_count(const int* __restrict__ eidx, int* __restrict__ cntB) {
    int o = blockIdx.y;
    const int* dst = eidx + (size_t)o * 2 * EE;
    int* cnt = cntB + (size_t)o * NN;
    int e = blockIdx.x * blockDim.x + threadIdx.x;
    if (e < EE) atomicAdd(&cnt[dst[e]], 1);
}

// scan writes rowptr AND rewrites cnt (cursor) to the exclusive prefix
__global__ void csr_scan(int* __restrict__ cntB, int* __restrict__ rowptrB) {
    int o = blockIdx.y;
    int* cnt = cntB + (size_t)o * NN;
    int* rowptr = rowptrB + (size_t)o * (NN + 1);
    __shared__ int sdata[1024];
    __shared__ int sbase;
    int t = threadIdx.x;
    if (t == 0) { rowptr[0] = 0; sbase = 0; }
    __syncthreads();
    for (int c = 0; c < NN; c += 1024) {
        int v = (c + t < NN) ? cnt[c + t] : 0;
        sdata[t] = v;
        __syncthreads();
        for (int off = 1; off < 1024; off <<= 1) {
            int add = (t >= off) ? sdata[t - off] : 0;
            __syncthreads();
            sdata[t] += add;
            __syncthreads();
        }
        if (c + t < NN) {
            rowptr[c + t + 1] = sbase + sdata[t];
            cnt[c + t] = sbase + sdata[t] - v;   // exclusive prefix -> cursor
        }
        __syncthreads();
        if (t == 0) sbase += sdata[1023];
        __syncthreads();
    }
}

__global__ void csr_fill(const int* __restrict__ eidx, const float* __restrict__ ewB,
                         int* __restrict__ cursorB, int2* __restrict__ epairB) {
    int o = blockIdx.y;
    const int* dst = eidx + (size_t)o * 2 * EE;
    const int* src = dst + EE;
    const float* w = ewB + (size_t)o * EE;
    int* cursor = cursorB + (size_t)o * NN;
    int2* ep = epairB + (size_t)o * EE;
    int e = blockIdx.x * blockDim.x + threadIdx.x;
    if (e < EE) {
        int pos = atomicAdd(&cursor[dst[e]], 1);
        ep[pos] = make_int2(src[e], __float_as_int(w[e]));
    }
}

// ---------------- casts + weight prep ----------------
__global__ void cast_f2h(const float* __restrict__ src, __half* __restrict__ dst, int n) {
    int i = blockIdx.x * blockDim.x + threadIdx.x;
    int i4 = i * 4;
    if (i4 + 3 < n) {
        float4 v = *(const float4*)(src + i4);
        __half2 h0 = __floats2half2_rn(v.x, v.y);
        __half2 h1 = __floats2half2_rn(v.z, v.w);
        *(uint2*)(dst + i4) = make_uint2(*(uint32_t*)&h0, *(uint32_t*)&h1);
    } else {
        for (int j = i4; j < n; j++) dst[j] = __float2half(src[j]);
    }
}

__global__ void fold_w(const float* __restrict__ Wout, const float* __restrict__ Wn1,
                       __half* __restrict__ Wfold) {
    int l = blockIdx.y;
    int idx = blockIdx.x * blockDim.x + threadIdx.x;
    if (idx >= 256 * 128) return;
    int k = idx >> 7, j = idx & 127;
    const float* wo = Wout + (size_t)l * 256 * 128 + (size_t)k * 128;
    const float* wn = Wn1 + (size_t)l * 128 * 128 + j;
    float a0 = 0.f, a1 = 0.f, a2 = 0.f, a3 = 0.f;
#pragma unroll 8
    for (int m = 0; m < 128; m += 4) {
        a0 = fmaf(wo[m],     wn[(size_t)m * 128],       a0);
        a1 = fmaf(wo[m + 1], wn[(size_t)(m + 1) * 128], a1);
        a2 = fmaf(wo[m + 2], wn[(size_t)(m + 2) * 128], a2);
        a3 = fmaf(wo[m + 3], wn[(size_t)(m + 3) * 128], a3);
    }
    Wfold[(size_t)l * 256 * 128 + idx] = __float2half((a0 + a1) + (a2 + a3));
}

__global__ void fold_b(const float* __restrict__ b_out, const float* __restrict__ Wn1,
                       const float* __restrict__ bn1, float* __restrict__ bf) {
    int l = blockIdx.y;
    int j = threadIdx.x;
    const float* bo = b_out + (size_t)l * 128;
    const float* wn = Wn1 + (size_t)l * 128 * 128 + j;
    float acc = bn1[(size_t)l * 128 + j];
    for (int m = 0; m < 128; m++) acc = fmaf(bo[m], wn[(size_t)m * 128], acc);
    bf[(size_t)l * 128 + j] = acc;
}

// ---------------- shared GEMM mainloop helpers ----------------
#define GEMM_PROLOG() \
    extern __shared__ char smem[]; \
    __half* As = (__half*)smem; \
    __half* Bs = (__half*)(smem + 128 * 136 * 2); \
    float*  Cs = (float*)smem; \
    const int tid = threadIdx.x; \
    const int warp = tid >> 5; \
    const int warpM = warp >> 1; \
    const int warpN = warp & 1; \
    const int rowBase = blockIdx.x * 128; \
    wmma::fragment<wmma::accumulator, 16, 16, 16, float> acc[2][4]; \
    _Pragma("unroll") for (int i = 0; i < 2; i++) \
    _Pragma("unroll") for (int j = 0; j < 4; j++) wmma::fill_fragment(acc[i][j], 0.f);

#define GEMM_MMA_CHUNK() do { \
    __syncthreads(); \
    _Pragma("unroll") \
    for (int ks = 0; ks < 8; ks++) { \
        int k0 = ks * 16; \
        wmma::fragment<wmma::matrix_a, 16, 16, 16, __half, wmma::row_major> af[2]; \
        wmma::fragment<wmma::matrix_b, 16, 16, 16, __half, wmma::row_major> bf[4]; \
        _Pragma("unroll") for (int i = 0; i < 2; i++) \
            wmma::load_matrix_sync(af[i], As + (warpM * 32 + i * 16) * 136 + k0, 136); \
        _Pragma("unroll") for (int j = 0; j < 4; j++) \
            wmma::load_matrix_sync(bf[j], Bs + k0 * 136 + warpN * 64 + j * 16, 136); \
        _Pragma("unroll") for (int i = 0; i < 2; i++) \
        _Pragma("unroll") for (int j = 0; j < 4; j++) \
            wmma::mma_sync(acc[i][j], af[i], bf[j], acc[i][j]); \
    } \
    __syncthreads(); \
} while (0)

#define GEMM_STORE_ACC() do { \
    _Pragma("unroll") for (int i = 0; i < 2; i++) \
    _Pragma("unroll") for (int j = 0; j < 4; j++) \
        wmma::store_matrix_sync(Cs + (warpM * 32 + i * 16) * 132 + warpN * 64 + j * 16, \
                                acc[i][j], 132, wmma::mem_row_major); \
    __syncthreads(); \
} while (0)

__device__ __forceinline__ void gemm_epilogue(
    float* Cs, int tid, int rowBase,
    const float* bias, const float* gam, const float* bet,
    __half* out)
{
    const float RS = 0.9999950000374997f;  // 1/sqrt(1+1e-5)
    const int r = tid >> 1;
    const int cb0 = (tid & 1) * 64;
    const int grow = rowBase + r;
    if (grow >= NN) return;
#pragma unroll
    for (int j = 0; j < 8; j++) {
        int c0 = cb0 + j * 8;
        float4 v0 = *(const float4*)(Cs + r * 132 + c0);
        float4 v1 = *(const float4*)(Cs + r * 132 + c0 + 4);
        float t[8] = {v0.x, v0.y, v0.z, v0.w, v1.x, v1.y, v1.z, v1.w};
#pragma unroll
        for (int q = 0; q < 8; q++) {
            int c = c0 + q;
            t[q] += bias[c];
            if (gam) t[q] = fmaxf(t[q] * gam[c] * RS + bet[c], 0.f);
        }
        __half2 h0 = __floats2half2_rn(t[0], t[1]);
        __half2 h1 = __floats2half2_rn(t[2], t[3]);
        __half2 h2 = __floats2half2_rn(t[4], t[5]);
        __half2 h3 = __floats2half2_rn(t[6], t[7]);
        *(uint4*)(out + (size_t)grow * 128 + c0) =
            make_uint4(*(uint32_t*)&h0, *(uint32_t*)&h1, *(uint32_t*)&h2, *(uint32_t*)&h3);
    }
}

// ---------------- standard wmma GEMM, K=128 (multi-order via blockIdx.y) ----------------
__global__ __launch_bounds__(256) void gemm16(
    const __half* __restrict__ A,
    const __half* __restrict__ Bb, size_t Bstride,
    const float* __restrict__ biasb, size_t biasStride,
    __half* __restrict__ outb, size_t outStride,
    const float* __restrict__ gam, const float* __restrict__ bet)
{
    GEMM_PROLOG();
    const int o = blockIdx.y;
    const __half* B = Bb + (size_t)o * Bstride;
#pragma unroll
    for (int it = 0; it < 8; it++) {
        int idx = it * 256 + tid;
        int r = idx >> 4;
        int c8 = (idx & 15) * 8;
        int grow = rowBase + r;
        uint4 av = make_uint4(0, 0, 0, 0);
        if (grow < NN) av = *(const uint4*)(A + (size_t)grow * 128 + c8);
        *(uint4*)(As + r * 136 + c8) = av;
        *(uint4*)(Bs + r * 136 + c8) = *(const uint4*)(B + (size_t)r * 128 + c8);
    }
    GEMM_MMA_CHUNK();
    GEMM_STORE_ACC();
    gemm_epilogue(Cs, tid, rowBase, biasb + (size_t)o * biasStride, gam, bet,
                  outb + (size_t)o * outStride);
}

// ---------------- fused combine+GEMM: t = relu(bn1( (Σ_k fW·zh) @ Wfold + bfold )) ----------------
__global__ __launch_bounds__(256) void gemm_fold(
    const __half* __restrict__ zh,
    const float* __restrict__ fWl,
    const __half* __restrict__ B,
    const float* __restrict__ bias,
    __half* __restrict__ out,
    const float* __restrict__ gam, const float* __restrict__ bet)
{
    GEMM_PROLOG();
    for (int kc = 0; kc < 2; kc++) {        // chunk kc == order kc
        const __half* zo = zh + (size_t)kc * ZSTRIDE;
        float fw[KHOP + 1];
#pragma unroll
        for (int k = 0; k <= KHOP; k++) fw[k] = __ldg(fWl + kc * (KHOP + 1) + k);
#pragma unroll
        for (int it = 0; it < 8; it++) {
            int idx = it * 256 + tid;
            int r = idx >> 4;
            int c8 = (idx & 15) * 8;
            int grow = rowBase + r;
            float fa[8] = {0, 0, 0, 0, 0, 0, 0, 0};
            if (grow < NN) {
                size_t off = (size_t)grow * 128 + c8;
#pragma unroll
                for (int k = 0; k <= KHOP; k++) {
                    uint4 u = *(const uint4*)(zo + (size_t)k * NH + off);
                    float f = fw[k];
                    float2 p0 = __half22float2(*(__half2*)&u.x);
                    float2 p1 = __half22float2(*(__half2*)&u.y);
                    float2 p2 = __half22float2(*(__half2*)&u.z);
                    float2 p3 = __half22float2(*(__half2*)&u.w);
                    fa[0] = fmaf(f, p0.x, fa[0]); fa[1] = fmaf(f, p0.y, fa[1]);
                    fa[2] = fmaf(f, p1.x, fa[2]); fa[3] = fmaf(f, p1.y, fa[3]);
                    fa[4] = fmaf(f, p2.x, fa[4]); fa[5] = fmaf(f, p2.y, fa[5]);
                    fa[6] = fmaf(f, p3.x, fa[6]); fa[7] = fmaf(f, p3.y, fa[7]);
                }
            }
            __half2 h0 = __floats2half2_rn(fa[0], fa[1]);
            __half2 h1 = __floats2half2_rn(fa[2], fa[3]);
            __half2 h2 = __floats2half2_rn(fa[4], fa[5]);
            __half2 h3 = __floats2half2_rn(fa[6], fa[7]);
            *(uint4*)(As + r * 136 + c8) =
                make_uint4(*(uint32_t*)&h0, *(uint32_t*)&h1, *(uint32_t*)&h2, *(uint32_t*)&h3);
            *(uint4*)(Bs + r * 136 + c8) = *(const uint4*)(B + (size_t)(kc * 128 + r) * 128 + c8);
        }
        GEMM_MMA_CHUNK();
    }
    GEMM_STORE_ACC();
    gemm_epilogue(Cs, tid, rowBase, bias, gam, bet, out);
}

// ---------------- SpMM hop: warp handles NPW nodes (grid-stride), dual order ----------------
#define NPW 4
__global__ __launch_bounds__(256) void spmm_hop(
    const int* __restrict__ rowptrB,
    const int2* __restrict__ epairB,
    const __half* __restrict__ zhB,
    int k, int nwarps)
{
    const int o = blockIdx.y;
    const int* rowptr = rowptrB + (size_t)o * (NN + 1);
    const int2* ep = epairB + (size_t)o * EE;
    const __half* zin = zhB + (size_t)o * ZSTRIDE + (size_t)k * NH;
    __half* zout = (__half*)zhB + (size_t)o * ZSTRIDE + (size_t)(k + 1) * NH;

    int gwarp = (blockIdx.x * blockDim.x + threadIdx.x) >> 5;
    int lane = threadIdx.x & 31;

    for (int node = gwarp; node < NN; node += nwarps) {
        int beg = rowptr[node], end = rowptr[node + 1];
        float ax = 0.f, ay = 0.f, az = 0.f, aw = 0.f;
        int e = beg;
        for (; e + 4 <= end; e += 4) {
            int2 p0 = ep[e], p1 = ep[e + 1], p2 = ep[e + 2], p3 = ep[e + 3];
            float w0 = __int_as_float(p0.y), w1 = __int_as_float(p1.y);
            float w2 = __int_as_float(p2.y), w3 = __int_as_float(p3.y);
            uint2 u0 = *(const uint2*)(zin + (size_t)p0.x * 128 + lane * 4);
            uint2 u1 = *(const uint2*)(zin + (size_t)p1.x * 128 + lane * 4);
            uint2 u2 = *(const uint2*)(zin + (size_t)p2.x * 128 + lane * 4);
            uint2 u3 = *(const uint2*)(zin + (size_t)p3.x * 128 + lane * 4);
            float2 a0 = __half22float2(*(__half2*)&u0.x), b0 = __half22float2(*(__half2*)&u0.y);
            float2 a1 = __half22float2(*(__half2*)&u1.x), b1 = __half22float2(*(__half2*)&u1.y);
            float2 a2 = __half22float2(*(__half2*)&u2.x), b2 = __half22float2(*(__half2*)&u2.y);
            float2 a3 = __half22float2(*(__half2*)&u3.x), b3 = __half22float2(*(__half2*)&u3.y);
            ax = fmaf(w0, a0.x, fmaf(w1, a1.x, fmaf(w2, a2.x, fmaf(w3, a3.x, ax))));
            ay = fmaf(w0, a0.y, fmaf(w1, a1.y, fmaf(w2, a2.y, fmaf(w3, a3.y, ay))));
            az = fmaf(w0, b0.x, fmaf(w1, b1.x, fmaf(w2, b2.x, fmaf(w3, b3.x, az))));
            aw = fmaf(w0, b0.y, fmaf(w1, b1.y, fmaf(w2, b2.y, fmaf(w3, b3.y, aw))));
        }
        for (; e < end; ++e) {
            int2 p = ep[e];
            float w = __int_as_float(p.y);
            uint2 u = *(const uint2*)(zin + (size_t)p.x * 128 + lane * 4);
            float2 a = __half22float2(*(__half2*)&u.x), b = __half22float2(*(__half2*)&u.y);
            ax = fmaf(w, a.x, ax); ay = fmaf(w, a.y, ay);
            az = fmaf(w, b.x, az); aw = fmaf(w, b.y, aw);
        }
        __half2 h0 = __floats2half2_rn(ax, ay);
        __half2 h1 = __floats2half2_rn(az, aw);
        *(uint2*)(zout + (size_t)node * 128 + lane * 4) = make_uint2(*(uint32_t*)&h0, *(uint32_t*)&h1);
    }
}

// ---------------- pooling + head ----------------
__global__ void pool_kernel(const __half* __restrict__ h, const int* __restrict__ batch,
                            float* __restrict__ p) {
    int idx = blockIdx.x * blockDim.x + threadIdx.x;
    if (idx >= NN * HH) return;
    int node = idx >> 7;
    int f = idx & 127;
    atomicAdd(&p[batch[node] * HH + f], __half2float(h[idx]));
}

__global__ void head1(const float* __restrict__ p, const float* __restrict__ W1,
                      const float* __restrict__ b1, float* __restrict__ p1) {
    int i = blockIdx.x * blockDim.x + threadIdx.x;
    if (i >= GG * HH) return;
    int g = i >> 7, j = i & 127;
    float acc = b1[j];
    for (int k = 0; k < HH; k++)
        acc = fmaf(p[g * HH + k], W1[k * HH + j], acc);
    p1[i] = fmaxf(acc, 0.f);
}

__global__ void head2(const float* __restrict__ p1, const float* __restrict__ W2,
                      const float* __restrict__ b2, float* __restrict__ outp) {
    int i = blockIdx.x * blockDim.x + threadIdx.x;
    if (i >= GG * CC) return;
    int g = i / CC, j = i % CC;
    float acc = b2[j];
    for (int k = 0; k < HH; k++)
        acc = fmaf(p1[g * HH + k], W2[k * CC + j], acc);
    outp[i] = acc;
}

// ---------------- host orchestration ----------------
extern "C" void kernel_launch(void* const* d_in, const int* in_sizes, int n_in,
                              void* d_out, int out_size) {
    const float* x      = (const float*)d_in[0];
    const int*   eidx   = (const int*)  d_in[1];
    const float* ew     = (const float*)d_in[2];
    const int*   batch  = (const int*)  d_in[3];
    const float* W_in   = (const float*)d_in[4];
    const float* b_in   = (const float*)d_in[5];
    const float* fW     = (const float*)d_in[6];
    const float* W_out  = (const float*)d_in[7];
    const float* b_out  = (const float*)d_in[8];
    const float* Wn1    = (const float*)d_in[9];
    const float* bn1    = (const float*)d_in[10];
    const float* g1     = (const float*)d_in[11];
    const float* be1    = (const float*)d_in[12];
    const float* Wn2    = (const float*)d_in[13];
    const float* bn2    = (const float*)d_in[14];
    const float* g2     = (const float*)d_in[15];
    const float* be2    = (const float*)d_in[16];
    const float* W1     = (const float*)d_in[17];
    const float* b1     = (const float*)d_in[18];
    const float* W2     = (const float*)d_in[19];
    const float* b2     = (const float*)d_in[20];
    float* outp = (float*)d_out;

    __half *x16, *zh, *t16, *h16, *win16, *wfold16, *wn216;
    float *bfold, *pool, *p1;
    int *rowptr, *cursor;
    int2 *epair;
    cudaGetSymbolAddress((void**)&x16, g_x16);
    cudaGetSymbolAddress((void**)&zh, g_zh);
    cudaGetSymbolAddress((void**)&t16, g_t16);
    cudaGetSymbolAddress((void**)&h16, g_h16);
    cudaGetSymbolAddress((void**)&win16, g_win16);
    cudaGetSymbolAddress((void**)&wfold16, g_wfold16);
    cudaGetSymbolAddress((void**)&bfold, g_bfold);
    cudaGetSymbolAddress((void**)&wn216, g_wn216);
    cudaGetSymbolAddress((void**)&pool, g_pool);
    cudaGetSymbolAddress((void**)&p1, g_p1);
    cudaGetSymbolAddress((void**)&rowptr, g_rowptr);
    cudaGetSymbolAddress((void**)&cursor, g_cursor);
    cudaGetSymbolAddress((void**)&epair, g_epair);

    const size_t WIN_SZ = (size_t)LL * OO * HH * HH;
    const size_t WN_SZ  = (size_t)LL * HH * HH;
    const int EB  = (EE + 255) / 256;
    const int MB  = (NN + 127) / 128;
    const int NW  = (NN + NPW - 1) / NPW;          // warps per order: 12500
    const int SBW = (NW * 32 + 255) / 256;         // blocks per order: 1563
    const int GEMM_SMEM = 128 * 136 * 2 * 2;

    cudaFuncSetAttribute(gemm16, cudaFuncAttributeMaxDynamicSharedMemorySize, GEMM_SMEM);
    cudaFuncSetAttribute(gemm_fold, cudaFuncAttributeMaxDynamicSharedMemorySize, GEMM_SMEM);

    // ---- weight prep ----
    cast_f2h<<<(int)((WIN_SZ / 4 + 255) / 256), 256>>>(W_in, win16, (int)WIN_SZ);
    cast_f2h<<<(int)((WN_SZ / 4 + 255) / 256), 256>>>(Wn2, wn216, (int)WN_SZ);
    cast_f2h<<<(int)((NH / 4 + 255) / 256), 256>>>(x, x16, (int)NH);
    fold_w<<<dim3((256 * 128 + 255) / 256, LL), 256>>>(W_out, Wn1, wfold16);
    fold_b<<<dim3(1, LL), 128>>>(b_out, Wn1, bn1, bfold);

    // ---- build CSR (both orders batched; scan emits cursor) ----
    cudaMemsetAsync(cursor, 0, (size_t)OO * NN * sizeof(int), 0);
    csr_count<<<dim3(EB, OO), 256>>>(eidx, cursor);
    csr_scan<<<dim3(1, OO), 1024>>>(cursor, rowptr);
    csr_fill<<<dim3(EB, OO), 256>>>(eidx, ew, cursor, epair);

    const int nwarps = SBW * 8;

    const __half* hin = x16;
    for (int l = 0; l < LL; l++) {
        // z0 for both orders -> zh slot 0
        gemm16<<<dim3(MB, OO), 256, GEMM_SMEM>>>(hin,
                                      win16 + (size_t)l * OO * HH * HH, (size_t)HH * HH,
                                      b_in + (size_t)l * OO * HH, HH,
                                      zh, ZSTRIDE,
                                      nullptr, nullptr);
        for (int k = 0; k < KHOP; k++)
            spmm_hop<<<dim3(SBW, OO), 256>>>(rowptr, epair, zh, k, nwarps);
        // t = relu(bn1( combine(zh) @ Wfold + bfold ))
        gemm_fold<<<dim3(MB, 1), 256, GEMM_SMEM>>>(zh,
                                      fW + (size_t)l * OO * (KHOP + 1),
                                      wfold16 + (size_t)l * 256 * HH,
                                      bfold + (size_t)l * HH,
                                      t16,
                                      g1 + (size_t)l * HH, be1 + (size_t)l * HH);
        // h = relu(bn2(t @ Wn2 + bn2))
        gemm16<<<dim3(MB, 1), 256, GEMM_SMEM>>>(t16,
                                      wn216 + (size_t)l * HH * HH, 0,
                                      bn2 + (size_t)l * HH, 0,
                                      h16, 0,
                                      g2 + (size_t)l * HH, be2 + (size_t)l * HH);
        hin = h16;
    }

    cudaMemsetAsync(pool, 0, GG * HH * sizeof(float), 0);
    pool_kernel<<<(NN * HH + 255) / 256, 256>>>(h16, batch, pool);
    head1<<<(GG * HH + 255) / 256, 256>>>(pool, W1, b1, p1);
    head2<<<(GG * CC + 255) / 256, 256>>>(p1, W2, b2, outp);
}